// round 8
// baseline (speedup 1.0000x reference)
#include <cuda_runtime.h>
#include <math.h>
#include <stdint.h>

#define NUM_CITIES 88
#define NC4        22              // 88 / 4 float4 column groups per row
#define NUM_YEARS  6
#define N_ROWS     200000

#define TPB        352             // 11 warps; 352 % 22 == 0
#define GRID       740             // 148 SMs * 5 blocks, one wave
#define TILE_F4    352             // float4 per array per tile (16 rows)
#define TILE_BYTES (TILE_F4 * 16)  // 5632
#define NTILES     12500           // N_ROWS*NC4 / TILE_F4  (exact)
#define NSTAGES    2
#define TXBYTES    (3 * TILE_BYTES) // 16896 per stage (G+D+w)

// Grid-level scratch. Zero at module load; last block resets each launch so
// every graph replay starts clean.
__device__ float g_colsum[NUM_CITIES];
__device__ float g_scalar;
__device__ unsigned int g_count;

// ---------- PTX helpers (self-contained) ----------
__device__ __forceinline__ uint32_t smem_u32(const void* p) {
    uint32_t a;
    asm("{ .reg .u64 t; cvta.to.shared.u64 t, %1; cvt.u32.u64 %0, t; }"
        : "=r"(a) : "l"(p));
    return a;
}
__device__ __forceinline__ void mbar_init(uint32_t m, uint32_t cnt) {
    asm volatile("mbarrier.init.shared.b64 [%0], %1;" :: "r"(m), "r"(cnt) : "memory");
}
__device__ __forceinline__ void mbar_expect_tx(uint32_t m, uint32_t bytes) {
    asm volatile("mbarrier.arrive.expect_tx.shared.b64 _, [%0], %1;"
                 :: "r"(m), "r"(bytes) : "memory");
}
__device__ __forceinline__ void mbar_wait(uint32_t m, uint32_t parity) {
    uint32_t done;
    asm volatile("{\n\t.reg .pred p;\n\t"
                 "mbarrier.try_wait.parity.acquire.cta.shared::cta.b64 p, [%1], %2;\n\t"
                 "selp.b32 %0, 1, 0, p;\n\t}"
                 : "=r"(done) : "r"(m), "r"(parity) : "memory");
    if (!done) {
        asm volatile("{\n\t.reg .pred P;\n\t"
                     "WL_%=:\n\t"
                     "mbarrier.try_wait.parity.acquire.cta.shared::cta.b64 P, [%0], %1, 0x989680;\n\t"
                     "@P bra.uni WD_%=;\n\t"
                     "bra.uni WL_%=;\n\t"
                     "WD_%=:\n\t}"
                     :: "r"(m), "r"(parity) : "memory");
    }
}
__device__ __forceinline__ void bulk_g2s(uint32_t dst, const void* src,
                                         uint32_t bytes, uint32_t m) {
    asm volatile("cp.async.bulk.shared::cluster.global.mbarrier::complete_tx::bytes "
                 "[%0], [%1], %2, [%3];"
                 :: "r"(dst), "l"(src), "r"(bytes), "r"(m) : "memory");
}
__device__ __forceinline__ void fence_proxy_async_cta() {
    asm volatile("fence.proxy.async.shared::cta;" ::: "memory");
}

// ---------- per-element loss body ----------
__device__ __forceinline__ void body(const float4 g, const float4 d,
                                     const float4 w,
                                     float& c0, float& c1, float& c2, float& c3,
                                     float& s)
{
    c0 += fabsf(g.x); c1 += fabsf(g.y);
    c2 += fabsf(g.z); c3 += fabsf(g.w);

    float r0 = fmaf(-w.x, d.x, g.x);
    float r1 = fmaf(-w.y, d.y, g.y);
    float r2 = fmaf(-w.z, d.z, g.z);
    float r3 = fmaf(-w.w, d.w, g.w);
    s += 100.0f * (r0*r0 + r1*r1 + r2*r2 + r3*r3);
    s += 0.01f  * (w.x*w.x + w.y*w.y + w.z*w.z + w.w*w.w);
    s += 100.0f * (fminf(g.x, 0.f) + fminf(g.y, 0.f)
                 + fminf(g.z, 0.f) + fminf(g.w, 0.f));
}

__global__ __launch_bounds__(TPB, 5)
void fused_loss_kernel(const float4* __restrict__ G4,
                       const float4* __restrict__ D4,
                       const float4* __restrict__ W4,
                       const float*  __restrict__ U,
                       const float*  __restrict__ OUT,
                       float* __restrict__ out)
{
    __shared__ __align__(16) unsigned long long s_mbar[NSTAGES];
    __shared__ __align__(16) float4 s_tile[NSTAGES][3][TILE_F4];
    __shared__ float scol[NUM_CITIES];
    __shared__ float swarp[TPB / 32];
    __shared__ unsigned int is_last;
    __shared__ float sh[128];

    const int tx = threadIdx.x;
    const int b  = blockIdx.x;
    const int cg = tx % NC4;               // fixed: 352 % 22 == 0

    const uint32_t mb0 = smem_u32(&s_mbar[0]);
    const uint32_t mb1 = smem_u32(&s_mbar[1]);

    if (tx == 0) { mbar_init(mb0, 1); mbar_init(mb1, 1); }
    if (tx < NUM_CITIES) scol[tx] = 0.0f;
    __syncthreads();

    // Kick off the first two stages ASAP (overlaps with the U-term below).
    if (tx == 0) {
        fence_proxy_async_cta();
        #pragma unroll
        for (int st = 0; st < NSTAGES; st++) {
            int t = b + st * GRID;
            if (t < NTILES) {
                uint32_t m = st ? mb1 : mb0;
                mbar_expect_tx(m, TXBYTES);
                bulk_g2s(smem_u32(&s_tile[st][0][0]), G4 + (size_t)t * TILE_F4, TILE_BYTES, m);
                bulk_g2s(smem_u32(&s_tile[st][1][0]), D4 + (size_t)t * TILE_F4, TILE_BYTES, m);
                bulk_g2s(smem_u32(&s_tile[st][2][0]), W4 + (size_t)t * TILE_F4, TILE_BYTES, m);
            }
        }
    }

    float c0 = 0.f, c1 = 0.f, c2 = 0.f, c3 = 0.f;
    float s  = 0.f;

    // Term 1: ||U[:, :5] - out[:, :5]||_F^2 — assigned to HIGH tids so the
    // heavy blocks (17 tiles, b < 660) skip it. Runs while first TMA flies.
    {
        const int tid  = b * TPB + tx;
        const int ridx = (GRID * TPB - 1) - tid;
        if (ridx < N_ROWS) {
            const float* u = U   + ridx * NUM_YEARS;
            const float* o = OUT + ridx * NUM_YEARS;
            #pragma unroll
            for (int j = 0; j < NUM_YEARS - 1; j++) {
                float d = u[j] - o[j];
                s += d * d;
            }
        }
    }

    // Main stream: G, D, w via TMA double-buffer. Thread t consumes SMEM slot
    // t -> flat float4 index 352*tile + t -> column group t%22, fixed.
    int it = 0;
    for (int t = b; t < NTILES; t += GRID, it++) {
        const int st = it & 1;
        const uint32_t m = st ? mb1 : mb0;
        mbar_wait(m, (it >> 1) & 1);

        float4 g = s_tile[st][0][tx];
        float4 d = s_tile[st][1][tx];
        float4 w = s_tile[st][2][tx];

        __syncthreads();                    // everyone done reading stage st

        if (tx == 0) {                      // refill this stage (tile t+2*GRID)
            int tn = t + NSTAGES * GRID;
            if (tn < NTILES) {
                mbar_expect_tx(m, TXBYTES);
                bulk_g2s(smem_u32(&s_tile[st][0][0]), G4 + (size_t)tn * TILE_F4, TILE_BYTES, m);
                bulk_g2s(smem_u32(&s_tile[st][1][0]), D4 + (size_t)tn * TILE_F4, TILE_BYTES, m);
                bulk_g2s(smem_u32(&s_tile[st][2][0]), W4 + (size_t)tn * TILE_F4, TILE_BYTES, m);
            }
        }

        body(g, d, w, c0, c1, c2, c3, s);
    }

    // --- block-level reduction (16 threads per scol slot) ---
    atomicAdd(&scol[cg * 4 + 0], c0);
    atomicAdd(&scol[cg * 4 + 1], c1);
    atomicAdd(&scol[cg * 4 + 2], c2);
    atomicAdd(&scol[cg * 4 + 3], c3);

    #pragma unroll
    for (int off = 16; off > 0; off >>= 1)
        s += __shfl_xor_sync(0xFFFFFFFF, s, off);
    if ((tx & 31) == 0) swarp[tx >> 5] = s;
    __syncthreads();

    // --- grid-level accumulation ---
    if (tx < NUM_CITIES)
        atomicAdd(&g_colsum[tx], scol[tx]);
    if (tx == 0) {
        float bs = 0.f;
        #pragma unroll
        for (int wv = 0; wv < TPB / 32; wv++) bs += swarp[wv];
        atomicAdd(&g_scalar, bs);
    }

    // --- last-block finalize ---
    __threadfence();
    __syncthreads();
    if (tx == 0)
        is_last = (atomicAdd(&g_count, 1u) == (unsigned)(gridDim.x - 1));
    __syncthreads();
    if (!is_last) return;

    __threadfence();   // acquire: all blocks' atomics visible

    if (tx < 128) {
        float v = 0.0f;
        if (tx < NUM_CITIES) {
            v = logf(*((volatile float*)&g_colsum[tx]));
            *((volatile float*)&g_colsum[tx]) = 0.0f;   // reset for next replay
        }
        sh[tx] = v;
    }
    __syncthreads();
    #pragma unroll
    for (int off = 64; off > 0; off >>= 1) {
        if (tx < off) sh[tx] += sh[tx + off];
        __syncthreads();
    }
    if (tx == 0) {
        float sc = *((volatile float*)&g_scalar);
        out[0] = sc + 1.0e-4f * sh[0];                  // stddeve^2 = 1e-4
        *((volatile float*)&g_scalar) = 0.0f;
        g_count = 0u;
    }
}

extern "C" void kernel_launch(void* const* d_in, const int* in_sizes, int n_in,
                              void* d_out, int out_size)
{
    // metadata order: G, out, U, V, D, w   (V unused by the loss)
    const float4* G4  = (const float4*)d_in[0];
    const float*  OUT = (const float*) d_in[1];
    const float*  U   = (const float*) d_in[2];
    const float4* D4  = (const float4*)d_in[4];
    const float4* W4  = (const float4*)d_in[5];
    float* out = (float*)d_out;

    fused_loss_kernel<<<GRID, TPB>>>(G4, D4, W4, U, OUT, out);
}

// round 9
// speedup vs baseline: 1.0429x; 1.0429x over previous
#include <cuda_runtime.h>
#include <math.h>

#define NUM_CITIES 88
#define NC4        22              // 88 / 4 float4 column groups per row
#define NUM_YEARS  6
#define N_ROWS     200000

#define TPB        352             // 11 warps; 352 % 22 == 0
#define GRID       592             // 148 SMs * 4 resident blocks, one wave
#define TILE_F4    352             // one ticket = 352 float4 per array (16 rows)
#define NTILES     12500           // N_ROWS*NC4 / TILE_F4 (exact)

// Grid-level scratch. Zero at module load; last block resets each launch so
// every graph replay starts clean.
__device__ float g_colsum[NUM_CITIES];
__device__ float g_scalar;
__device__ unsigned int g_count;
__device__ unsigned int g_tick;

__device__ __forceinline__ void body(const float4 g, const float4 d,
                                     const float4 w,
                                     float& c0, float& c1, float& c2, float& c3,
                                     float& s)
{
    c0 += fabsf(g.x); c1 += fabsf(g.y);
    c2 += fabsf(g.z); c3 += fabsf(g.w);

    float r0 = fmaf(-w.x, d.x, g.x);
    float r1 = fmaf(-w.y, d.y, g.y);
    float r2 = fmaf(-w.z, d.z, g.z);
    float r3 = fmaf(-w.w, d.w, g.w);
    s += 100.0f * (r0*r0 + r1*r1 + r2*r2 + r3*r3);
    s += 0.01f  * (w.x*w.x + w.y*w.y + w.z*w.z + w.w*w.w);
    s += 100.0f * (fminf(g.x, 0.f) + fminf(g.y, 0.f)
                 + fminf(g.z, 0.f) + fminf(g.w, 0.f));
}

__global__ __launch_bounds__(TPB)
void fused_loss_kernel(const float4* __restrict__ G4,
                       const float4* __restrict__ D4,
                       const float4* __restrict__ W4,
                       const float*  __restrict__ U,
                       const float*  __restrict__ OUT,
                       float* __restrict__ out)
{
    __shared__ float scol[NUM_CITIES];
    __shared__ float swarp[TPB / 32];
    __shared__ unsigned int is_last;
    __shared__ int s_tick[2];
    __shared__ float sh[128];

    const int tx = threadIdx.x;
    const int cg = tx % NC4;               // fixed: 352 % 22 == 0

    if (tx < NUM_CITIES) scol[tx] = 0.0f;
    if (tx == 0) s_tick[0] = (int)atomicAdd(&g_tick, 1u);   // first ticket
    __syncthreads();

    float c0 = 0.f, c1 = 0.f, c2 = 0.f, c3 = 0.f;
    float s  = 0.f;

    // Term 1: ||U[:, :5] - out[:, :5]||_F^2  (9.6 MB)
    {
        const int tid   = blockIdx.x * TPB + tx;
        const int total = GRID * TPB;
        for (int r = tid; r < N_ROWS; r += total) {
            const float* u = U   + r * NUM_YEARS;
            const float* o = OUT + r * NUM_YEARS;
            #pragma unroll
            for (int j = 0; j < NUM_YEARS - 1; j++) {
                float d = u[j] - o[j];
                s += d * d;
            }
        }
    }

    // Main stream: G, D, w (211 MB) via persistent dynamic tile scheduler.
    // Ticket t covers flat float4 indices [t*352, (t+1)*352); thread tx takes
    // element t*352+tx, so its column group (tx%22) is compile-time fixed and
    // |G| column partials stay in 4 registers. Next ticket is prefetched by
    // tx==0 while the current tile streams (atomic latency hidden).
    int phase = 0;
    while (true) {
        const int t = s_tick[phase & 1];
        if (t >= NTILES) break;                       // uniform exit

        if (tx == 0)
            s_tick[(phase + 1) & 1] = (int)atomicAdd(&g_tick, 1u);

        const int i = t * TILE_F4 + tx;
        float4 g = __ldcs(&G4[i]);
        float4 d = __ldcs(&D4[i]);
        float4 w = __ldcs(&W4[i]);
        body(g, d, w, c0, c1, c2, c3, s);

        __syncthreads();                              // publish next ticket
        phase++;
    }

    // --- block-level reduction (16 threads per scol slot) ---
    atomicAdd(&scol[cg * 4 + 0], c0);
    atomicAdd(&scol[cg * 4 + 1], c1);
    atomicAdd(&scol[cg * 4 + 2], c2);
    atomicAdd(&scol[cg * 4 + 3], c3);

    #pragma unroll
    for (int off = 16; off > 0; off >>= 1)
        s += __shfl_xor_sync(0xFFFFFFFF, s, off);
    if ((tx & 31) == 0) swarp[tx >> 5] = s;
    __syncthreads();

    // --- grid-level accumulation ---
    if (tx < NUM_CITIES)
        atomicAdd(&g_colsum[tx], scol[tx]);
    if (tx == 0) {
        float bs = 0.f;
        #pragma unroll
        for (int wv = 0; wv < TPB / 32; wv++) bs += swarp[wv];
        atomicAdd(&g_scalar, bs);
    }

    // --- last-block finalize (threadFenceReduction pattern) ---
    __threadfence();
    __syncthreads();
    if (tx == 0)
        is_last = (atomicAdd(&g_count, 1u) == (unsigned)(gridDim.x - 1));
    __syncthreads();
    if (!is_last) return;

    __threadfence();   // acquire: all blocks' atomics visible

    if (tx < 128) {
        float v = 0.0f;
        if (tx < NUM_CITIES) {
            v = logf(*((volatile float*)&g_colsum[tx]));
            *((volatile float*)&g_colsum[tx]) = 0.0f;   // reset for next replay
        }
        sh[tx] = v;
    }
    __syncthreads();
    #pragma unroll
    for (int off = 64; off > 0; off >>= 1) {
        if (tx < off) sh[tx] += sh[tx + off];
        __syncthreads();
    }
    if (tx == 0) {
        float sc = *((volatile float*)&g_scalar);
        out[0] = sc + 1.0e-4f * sh[0];                  // stddeve^2 = 1e-4
        *((volatile float*)&g_scalar) = 0.0f;
        g_count = 0u;
        g_tick  = 0u;                                   // reset scheduler
    }
}

extern "C" void kernel_launch(void* const* d_in, const int* in_sizes, int n_in,
                              void* d_out, int out_size)
{
    // metadata order: G, out, U, V, D, w   (V unused by the loss)
    const float4* G4  = (const float4*)d_in[0];
    const float*  OUT = (const float*) d_in[1];
    const float*  U   = (const float*) d_in[2];
    const float4* D4  = (const float4*)d_in[4];
    const float4* W4  = (const float4*)d_in[5];
    float* out = (float*)d_out;

    fused_loss_kernel<<<GRID, TPB>>>(G4, D4, W4, U, OUT, out);
}

// round 10
// speedup vs baseline: 1.0584x; 1.0148x over previous
#include <cuda_runtime.h>
#include <math.h>

#define NUM_CITIES 88
#define NC4        22              // 88 / 4 float4 column groups per row
#define NUM_YEARS  6
#define N_ROWS     200000

#define TPB        352             // 11 warps; 352 % 22 == 0
#define GRID       500             // 500*352 = 176000 threads = 8000 row-lanes
#define LANES      8000            // 200000 / 8000 = 25 iterations, EXACT
#define ITERS      25

// Grid-level scratch. Zero at module load; last block resets each launch so
// every graph replay starts clean.
__device__ float g_colsum[NUM_CITIES];
__device__ float g_scalar;
__device__ unsigned int g_count;

__device__ __forceinline__ void body(const float4 g, const float4 d,
                                     const float4 w,
                                     float& c0, float& c1, float& c2, float& c3,
                                     float& s)
{
    c0 += fabsf(g.x); c1 += fabsf(g.y);
    c2 += fabsf(g.z); c3 += fabsf(g.w);

    float r0 = fmaf(-w.x, d.x, g.x);
    float r1 = fmaf(-w.y, d.y, g.y);
    float r2 = fmaf(-w.z, d.z, g.z);
    float r3 = fmaf(-w.w, d.w, g.w);
    s += 100.0f * (r0*r0 + r1*r1 + r2*r2 + r3*r3);
    s += 0.01f  * (w.x*w.x + w.y*w.y + w.z*w.z + w.w*w.w);
    s += 100.0f * (fminf(g.x, 0.f) + fminf(g.y, 0.f)
                 + fminf(g.z, 0.f) + fminf(g.w, 0.f));
}

__global__ __launch_bounds__(TPB)
void fused_loss_kernel(const float4* __restrict__ G4,
                       const float4* __restrict__ D4,
                       const float4* __restrict__ W4,
                       const float*  __restrict__ U,
                       const float*  __restrict__ OUT,
                       float* __restrict__ out)
{
    const int tid  = blockIdx.x * TPB + threadIdx.x;
    const int cg   = threadIdx.x % NC4;     // fixed column group (352%22==0)
    const int lane = tid / NC4;             // row-lane in [0, LANES)

    float c0 = 0.f, c1 = 0.f, c2 = 0.f, c3 = 0.f;   // |G| column partials
    float s  = 0.f;                                  // scalar loss partial

    // Term 1: ||U[:, :5] - out[:, :5]||_F^2  (9.6 MB; <=2 rows per thread)
    {
        const int total = GRID * TPB;                // 176000
        for (int r = tid; r < N_ROWS; r += total) {
            const float* u = U   + r * NUM_YEARS;
            const float* o = OUT + r * NUM_YEARS;
            #pragma unroll
            for (int j = 0; j < NUM_YEARS - 1; j++) {
                float d = u[j] - o[j];
                s += d * d;
            }
        }
    }

    // Main stream: G, D, w (211 MB). Perfectly balanced: every thread does
    // exactly 25 iterations (200000 rows / 8000 lanes) — no tail, no sync.
    int i = lane * NC4 + cg;
    const int stride = LANES * NC4;
    #pragma unroll 1
    for (int it = 0; it < ITERS; it++, i += stride) {
        float4 g = __ldcs(&G4[i]);
        float4 d = __ldcs(&D4[i]);
        float4 w = __ldcs(&W4[i]);
        body(g, d, w, c0, c1, c2, c3, s);
    }

    // --- block-level reduction ---
    __shared__ float scol[NUM_CITIES];
    __shared__ float swarp[TPB / 32];
    __shared__ unsigned int is_last;
    __shared__ float sh[128];

    if (threadIdx.x < NUM_CITIES) scol[threadIdx.x] = 0.0f;
    __syncthreads();

    // column partials: 16 threads per shared slot, once per block
    atomicAdd(&scol[cg * 4 + 0], c0);
    atomicAdd(&scol[cg * 4 + 1], c1);
    atomicAdd(&scol[cg * 4 + 2], c2);
    atomicAdd(&scol[cg * 4 + 3], c3);

    // scalar: warp shuffle reduce
    #pragma unroll
    for (int off = 16; off > 0; off >>= 1)
        s += __shfl_xor_sync(0xFFFFFFFF, s, off);
    if ((threadIdx.x & 31) == 0) swarp[threadIdx.x >> 5] = s;
    __syncthreads();

    // --- grid-level accumulation ---
    if (threadIdx.x < NUM_CITIES)
        atomicAdd(&g_colsum[threadIdx.x], scol[threadIdx.x]);
    if (threadIdx.x == 0) {
        float bs = 0.f;
        #pragma unroll
        for (int wv = 0; wv < TPB / 32; wv++) bs += swarp[wv];
        atomicAdd(&g_scalar, bs);
    }

    // --- last-block finalize (threadFenceReduction pattern) ---
    __threadfence();
    __syncthreads();
    if (threadIdx.x == 0)
        is_last = (atomicAdd(&g_count, 1u) == (unsigned)(gridDim.x - 1));
    __syncthreads();
    if (!is_last) return;

    __threadfence();   // acquire: all blocks' atomics visible

    int t = threadIdx.x;
    if (t < 128) {
        float v = 0.0f;
        if (t < NUM_CITIES) {
            v = logf(*((volatile float*)&g_colsum[t]));
            *((volatile float*)&g_colsum[t]) = 0.0f;   // reset for next replay
        }
        sh[t] = v;
    }
    __syncthreads();
    #pragma unroll
    for (int off = 64; off > 0; off >>= 1) {
        if (t < off) sh[t] += sh[t + off];
        __syncthreads();
    }
    if (t == 0) {
        float sc = *((volatile float*)&g_scalar);
        out[0] = sc + 1.0e-4f * sh[0];                 // stddeve^2 = 1e-4
        *((volatile float*)&g_scalar) = 0.0f;
        g_count = 0u;
    }
}

extern "C" void kernel_launch(void* const* d_in, const int* in_sizes, int n_in,
                              void* d_out, int out_size)
{
    // metadata order: G, out, U, V, D, w   (V unused by the loss)
    const float4* G4  = (const float4*)d_in[0];
    const float*  OUT = (const float*) d_in[1];
    const float*  U   = (const float*) d_in[2];
    const float4* D4  = (const float4*)d_in[4];
    const float4* W4  = (const float4*)d_in[5];
    float* out = (float*)d_out;

    fused_loss_kernel<<<GRID, TPB>>>(G4, D4, W4, U, OUT, out);
}